// round 1
// baseline (speedup 1.0000x reference)
#include <cuda_runtime.h>
#include <math.h>

// Problem constants
#define BATCH   2
#define SEQLEN  1024
#define DMODEL  768
#define DINNER  1536
#define DSTATE  64
#define MROWS   (BATCH * SEQLEN)     // 2048
#define XDBL_LD 132                  // padded row stride for x_dbl

// Scratch (device globals; no allocation allowed)
__device__ float g_xz   [MROWS * 2 * DINNER];      // 25.2 MB: cols 0..1535 = x_p, 1536..3071 = z
__device__ float g_xconv[MROWS * DINNER];          // 12.6 MB
__device__ float g_xdbl [MROWS * XDBL_LD];         // 1.1 MB: col0=dt_in, cols 2..65=B, 66..129=C
__device__ float g_pre  [MROWS * DINNER * 4];      // 50.3 MB: {dt, dt*xc, D*xc*sz, sz}
__device__ float g_y    [MROWS * DINNER];          // 12.6 MB

// ---------------------------------------------------------------------------
// SGEMM 128x128x8, C[M,N] = A[M,K] * B[N,K]^T  (all row-major, K contiguous)
// Dims must satisfy M%128==0, N%128==0, K%8==0.
// ---------------------------------------------------------------------------
__global__ __launch_bounds__(256) void sgemm128(
    const float* __restrict__ A, const float* __restrict__ B,
    float* __restrict__ C, int M, int N, int K)
{
    __shared__ float As[8][132];
    __shared__ float Bs[8][132];

    const int tid = threadIdx.x;
    const int bm = blockIdx.y * 128;
    const int bn = blockIdx.x * 128;

    const int lr = tid >> 1;          // 0..127 row within tile
    const int lk = (tid & 1) * 4;     // 0 or 4
    const float* Ag = A + (size_t)(bm + lr) * K + lk;
    const float* Bg = B + (size_t)(bn + lr) * K + lk;

    const int tx = tid & 15;          // 0..15
    const int ty = tid >> 4;          // 0..15

    float c[8][8];
#pragma unroll
    for (int i = 0; i < 8; i++)
#pragma unroll
        for (int j = 0; j < 8; j++) c[i][j] = 0.f;

    for (int k0 = 0; k0 < K; k0 += 8) {
        float4 av = *(const float4*)(Ag + k0);
        float4 bv = *(const float4*)(Bg + k0);
        As[lk + 0][lr] = av.x; As[lk + 1][lr] = av.y;
        As[lk + 2][lr] = av.z; As[lk + 3][lr] = av.w;
        Bs[lk + 0][lr] = bv.x; Bs[lk + 1][lr] = bv.y;
        Bs[lk + 2][lr] = bv.z; Bs[lk + 3][lr] = bv.w;
        __syncthreads();

#pragma unroll
        for (int k = 0; k < 8; k++) {
            float4 a0 = *(const float4*)&As[k][ty * 4];
            float4 a1 = *(const float4*)&As[k][ty * 4 + 64];
            float4 b0 = *(const float4*)&Bs[k][tx * 4];
            float4 b1 = *(const float4*)&Bs[k][tx * 4 + 64];
            float ar[8] = {a0.x, a0.y, a0.z, a0.w, a1.x, a1.y, a1.z, a1.w};
            float br[8] = {b0.x, b0.y, b0.z, b0.w, b1.x, b1.y, b1.z, b1.w};
#pragma unroll
            for (int i = 0; i < 8; i++)
#pragma unroll
                for (int j = 0; j < 8; j++)
                    c[i][j] = fmaf(ar[i], br[j], c[i][j]);
        }
        __syncthreads();
    }

#pragma unroll
    for (int i = 0; i < 8; i++) {
        int row = bm + ty * 4 + ((i < 4) ? i : (60 + i));  // +64 for upper half
        float4 v0 = make_float4(c[i][0], c[i][1], c[i][2], c[i][3]);
        float4 v1 = make_float4(c[i][4], c[i][5], c[i][6], c[i][7]);
        *(float4*)(C + (size_t)row * N + bn + tx * 4)      = v0;
        *(float4*)(C + (size_t)row * N + bn + tx * 4 + 64) = v1;
    }
}

// ---------------------------------------------------------------------------
// SGEMM 64x64x16 with N bounds + optional column remap (for x_dbl layout).
// M%64==0, K%16==0; N arbitrary. remap: n==0 -> col0, n>=1 -> col n+1.
// ---------------------------------------------------------------------------
__global__ __launch_bounds__(256) void sgemm64(
    const float* __restrict__ A, const float* __restrict__ B,
    float* __restrict__ C, int M, int N, int K, int ldc, int remap)
{
    __shared__ float As[16][68];
    __shared__ float Bs[16][68];

    const int tid = threadIdx.x;
    const int bm = blockIdx.y * 64;
    const int bn = blockIdx.x * 64;

    const int lr = tid >> 2;          // 0..63
    const int lk = (tid & 3) * 4;     // 0,4,8,12
    const int tx = tid & 15, ty = tid >> 4;

    float c[4][4];
#pragma unroll
    for (int i = 0; i < 4; i++)
#pragma unroll
        for (int j = 0; j < 4; j++) c[i][j] = 0.f;

    const float* Ag = A + (size_t)(bm + lr) * K + lk;
    const int brow = bn + lr;
    const float* Bg = B + (size_t)brow * K + lk;
    const bool bok = (brow < N);

    for (int k0 = 0; k0 < K; k0 += 16) {
        float4 av = *(const float4*)(Ag + k0);
        float4 bv = bok ? *(const float4*)(Bg + k0)
                        : make_float4(0.f, 0.f, 0.f, 0.f);
        As[lk + 0][lr] = av.x; As[lk + 1][lr] = av.y;
        As[lk + 2][lr] = av.z; As[lk + 3][lr] = av.w;
        Bs[lk + 0][lr] = bv.x; Bs[lk + 1][lr] = bv.y;
        Bs[lk + 2][lr] = bv.z; Bs[lk + 3][lr] = bv.w;
        __syncthreads();

#pragma unroll
        for (int k = 0; k < 16; k++) {
            float4 a = *(const float4*)&As[k][ty * 4];
            float4 b = *(const float4*)&Bs[k][tx * 4];
            float ar[4] = {a.x, a.y, a.z, a.w};
            float br[4] = {b.x, b.y, b.z, b.w};
#pragma unroll
            for (int i = 0; i < 4; i++)
#pragma unroll
                for (int j = 0; j < 4; j++)
                    c[i][j] = fmaf(ar[i], br[j], c[i][j]);
        }
        __syncthreads();
    }

#pragma unroll
    for (int i = 0; i < 4; i++) {
        int row = bm + ty * 4 + i;
#pragma unroll
        for (int j = 0; j < 4; j++) {
            int n = bn + tx * 4 + j;
            if (n < N) {
                int col = remap ? ((n == 0) ? 0 : n + 1) : n;
                C[(size_t)row * ldc + col] = c[i][j];
            }
        }
    }
}

// ---------------------------------------------------------------------------
// Causal conv (width 4) + SiLU: x_conv = silu(conv_b + sum_i x_p[l-3+i]*w[i])
// One thread per (m, group of 4 channels).
// ---------------------------------------------------------------------------
__global__ void conv_silu_kernel(const float* __restrict__ cw,
                                 const float* __restrict__ cb)
{
    int i = blockIdx.x * blockDim.x + threadIdx.x;
    const int ngrp = DINNER / 4;
    if (i >= MROWS * ngrp) return;
    int m  = i / ngrp;
    int dg = i % ngrp;
    int l  = m % SEQLEN;
    int d0 = dg * 4;

    float4 acc = make_float4(cb[d0], cb[d0 + 1], cb[d0 + 2], cb[d0 + 3]);
#pragma unroll
    for (int t = 0; t < 4; t++) {
        int li = l - 3 + t;
        if (li >= 0) {
            const float4 v = *(const float4*)&g_xz[(size_t)(m - l + li) * (2 * DINNER) + d0];
            acc.x = fmaf(v.x, __ldg(&cw[(d0 + 0) * 4 + t]), acc.x);
            acc.y = fmaf(v.y, __ldg(&cw[(d0 + 1) * 4 + t]), acc.y);
            acc.z = fmaf(v.z, __ldg(&cw[(d0 + 2) * 4 + t]), acc.z);
            acc.w = fmaf(v.w, __ldg(&cw[(d0 + 3) * 4 + t]), acc.w);
        }
    }
    float4 o;
    o.x = acc.x / (1.f + expf(-acc.x));
    o.y = acc.y / (1.f + expf(-acc.y));
    o.z = acc.z / (1.f + expf(-acc.z));
    o.w = acc.w / (1.f + expf(-acc.w));
    ((float4*)g_xconv)[i] = o;
}

// ---------------------------------------------------------------------------
// Precompute per-(m,d): dt = softplus(dt_in*dt_w+dt_b), dt*xc, D*xc*silu(z), silu(z)
// ---------------------------------------------------------------------------
__global__ void pre_kernel(const float* __restrict__ dt_w,
                           const float* __restrict__ dt_b,
                           const float* __restrict__ Dp)
{
    int i = blockIdx.x * blockDim.x + threadIdx.x;
    if (i >= MROWS * DINNER) return;
    int m = i / DINNER, d = i % DINNER;

    float dtin = g_xdbl[(size_t)m * XDBL_LD];
    float xarg = fmaf(dtin, __ldg(&dt_w[d]), __ldg(&dt_b[d]));
    // softplus = logaddexp(x, 0) = max(x,0) + log1p(exp(-|x|))
    float dt = fmaxf(xarg, 0.f) + log1pf(expf(-fabsf(xarg)));

    float xc = g_xconv[i];
    float z  = g_xz[(size_t)m * (2 * DINNER) + DINNER + d];
    float sz = z / (1.f + expf(-z));

    float4 o = make_float4(dt, dt * xc, __ldg(&Dp[d]) * xc * sz, sz);
    ((float4*)g_pre)[i] = o;
}

// ---------------------------------------------------------------------------
// Selective scan: one warp per (b,d) channel, 2 states per lane.
// ---------------------------------------------------------------------------
__device__ __forceinline__ float fast_ex2(float x) {
    float r;
    asm("ex2.approx.ftz.f32 %0, %1;" : "=f"(r) : "f"(x));
    return r;
}

__global__ __launch_bounds__(256) void scan_kernel(const float* __restrict__ A_log)
{
    const int warp = threadIdx.x >> 5;
    const int lane = threadIdx.x & 31;
    const int ch = blockIdx.x * 8 + warp;     // 0..3071
    const int b = ch / DINNER;
    const int d = ch % DINNER;
    const int n0 = 2 * lane;

    const float LOG2E = 1.4426950408889634f;
    const float An0 = -expf(A_log[n0])     * LOG2E;
    const float An1 = -expf(A_log[n0 + 1]) * LOG2E;

    const int mbase = b * SEQLEN;
    const float4* prp = (const float4*)g_pre + ((size_t)mbase * DINNER + d);
    const float*  xb  = g_xdbl + (size_t)mbase * XDBL_LD;
    float*        yo  = g_y + (size_t)mbase * DINNER + d;

    float h0 = 0.f, h1 = 0.f;
    float4 pr = __ldg(prp);
    float2 Bv = __ldg((const float2*)(xb + 2  + n0));
    float2 Cv = __ldg((const float2*)(xb + 66 + n0));

    for (int l = 0; l < SEQLEN; l++) {
        int ln = (l < SEQLEN - 1) ? (l + 1) : l;
        float4 prn = __ldg(prp + (size_t)ln * DINNER);
        float2 Bvn = __ldg((const float2*)(xb + (size_t)ln * XDBL_LD + 2  + n0));
        float2 Cvn = __ldg((const float2*)(xb + (size_t)ln * XDBL_LD + 66 + n0));

        float dA0 = fast_ex2(pr.x * An0);
        float dA1 = fast_ex2(pr.x * An1);
        h0 = fmaf(h0, dA0, Bv.x * pr.y);
        h1 = fmaf(h1, dA1, Bv.y * pr.y);
        float y = fmaf(h0, Cv.x, h1 * Cv.y);
#pragma unroll
        for (int o = 16; o > 0; o >>= 1)
            y += __shfl_xor_sync(0xffffffffu, y, o);
        if (lane == 0)
            yo[(size_t)l * DINNER] = fmaf(y, pr.w, pr.z);

        pr = prn; Bv = Bvn; Cv = Cvn;
    }
}

// ---------------------------------------------------------------------------
extern "C" void kernel_launch(void* const* d_in, const int* in_sizes, int n_in,
                              void* d_out, int out_size)
{
    const float* x      = (const float*)d_in[0];
    const float* W_in   = (const float*)d_in[1];
    const float* conv_w = (const float*)d_in[2];
    const float* conv_b = (const float*)d_in[3];
    const float* W_x    = (const float*)d_in[4];
    const float* dt_w   = (const float*)d_in[5];
    const float* dt_b   = (const float*)d_in[6];
    const float* A_log  = (const float*)d_in[7];
    const float* D_par  = (const float*)d_in[8];
    const float* W_out  = (const float*)d_in[9];
    float* out = (float*)d_out;

    float *p_xz, *p_xconv, *p_xdbl, *p_y;
    cudaGetSymbolAddress((void**)&p_xz,    g_xz);
    cudaGetSymbolAddress((void**)&p_xconv, g_xconv);
    cudaGetSymbolAddress((void**)&p_xdbl,  g_xdbl);
    cudaGetSymbolAddress((void**)&p_y,     g_y);

    // 1) xz = x @ W_in^T : [2048,3072]
    sgemm128<<<dim3(2 * DINNER / 128, MROWS / 128), 256>>>(
        x, W_in, p_xz, MROWS, 2 * DINNER, DMODEL);

    // 2) causal conv + silu
    {
        int total = MROWS * (DINNER / 4);
        conv_silu_kernel<<<(total + 255) / 256, 256>>>(conv_w, conv_b);
    }

    // 3) x_dbl = x_conv @ W_x^T : [2048,129] -> g_xdbl (remapped cols)
    sgemm64<<<dim3((129 + 63) / 64, MROWS / 64), 256>>>(
        p_xconv, W_x, p_xdbl, MROWS, 129, DINNER, XDBL_LD, 1);

    // 4) precompute dt / dt*xc / D*xc*silu(z) / silu(z)
    {
        int total = MROWS * DINNER;
        pre_kernel<<<(total + 255) / 256, 256>>>(dt_w, dt_b, D_par);
    }

    // 5) selective scan -> g_y (already gated by silu(z) and D term)
    scan_kernel<<<(BATCH * DINNER) / 8, 256>>>(A_log);

    // 6) out = y @ W_out^T : [2048,768]
    sgemm128<<<dim3(DMODEL / 128, MROWS / 128), 256>>>(
        p_y, W_out, out, MROWS, DMODEL, DINNER);
}

// round 2
// speedup vs baseline: 1.3514x; 1.3514x over previous
#include <cuda_runtime.h>
#include <cuda_bf16.h>
#include <math.h>

// Problem constants
#define BATCH   2
#define SEQLEN  1024
#define DMODEL  768
#define DINNER  1536
#define DSTATE  64
#define MROWS   (BATCH * SEQLEN)     // 2048
#define XDBL_LD 132                  // padded row stride for x_dbl

// Scratch (device globals; no allocation allowed)
__device__ float g_xz   [MROWS * 2 * DINNER];      // cols 0..1535 = x_p, 1536..3071 = z
__device__ float g_xconv[MROWS * DINNER];
__device__ float g_xdbl [MROWS * XDBL_LD];         // col0=dt_in, cols 2..65=B, 66..129=C
__device__ float g_pre  [MROWS * DINNER * 4];      // {dt, dt*xc, D*xc*sz, sz}
__device__ float g_y    [MROWS * DINNER];

// ---------------------------------------------------------------------------
// bf16x3 split tensor-core GEMM: C[M,N] = A[M,K] * B[N,K]^T
// A row-major [M,K], B row-major [N,K]. M%128==0, N%128==0, K%16==0.
// Split A = Ah + Al, B = Bh + Bl (bf16); C ≈ AhBh + AlBh + AhBl (fp32 acc).
// Block: 256 threads = 8 warps (2 x 4), warp tile 64x32, BK=16.
// ---------------------------------------------------------------------------
__device__ __forceinline__ void split2_bf16(float x, float y,
                                            unsigned& hi, unsigned& lo)
{
    __nv_bfloat16 xh = __float2bfloat16_rn(x);
    __nv_bfloat16 yh = __float2bfloat16_rn(y);
    __nv_bfloat16 xl = __float2bfloat16_rn(x - __bfloat162float(xh));
    __nv_bfloat16 yl = __float2bfloat16_rn(y - __bfloat162float(yh));
    hi = (unsigned)__bfloat16_as_ushort(xh) |
         ((unsigned)__bfloat16_as_ushort(yh) << 16);
    lo = (unsigned)__bfloat16_as_ushort(xl) |
         ((unsigned)__bfloat16_as_ushort(yl) << 16);
}

__device__ __forceinline__ void mma16816(float* c, const unsigned* a,
                                         const unsigned* b)
{
    asm volatile(
        "mma.sync.aligned.m16n8k16.row.col.f32.bf16.bf16.f32 "
        "{%0,%1,%2,%3}, {%4,%5,%6,%7}, {%8,%9}, {%0,%1,%2,%3};\n"
        : "+f"(c[0]), "+f"(c[1]), "+f"(c[2]), "+f"(c[3])
        : "r"(a[0]), "r"(a[1]), "r"(a[2]), "r"(a[3]),
          "r"(b[0]), "r"(b[1]));
}

__global__ __launch_bounds__(256) void gemm_bf16x3(
    const float* __restrict__ A, const float* __restrict__ B,
    float* __restrict__ C, int M, int N, int K)
{
    // Fragment-layout staging buffers (one BK=16 slab each).
    // A: 8 m-tiles x 32 lanes x 4 regs; B: 16 n-tiles x 32 lanes x 2 regs.
    __shared__ __align__(16) unsigned Ah[1024], Al[1024];
    __shared__ __align__(16) unsigned Bh[1024], Bl[1024];

    const int tid  = threadIdx.x;
    const int lane = tid & 31;
    const int wid  = tid >> 5;
    const int warp_m = wid & 1;   // 0..1  (64 rows each)
    const int warp_n = wid >> 1;  // 0..3  (32 cols each)

    const int bm = blockIdx.y * 128;
    const int bn = blockIdx.x * 128;

    // Staging: each thread owns 8 consecutive floats of one A row + one B row.
    const int srow = tid >> 1;        // 0..127
    const int sj   = tid & 1;         // which 8-col group of the 16-wide slab
    const float* Ag = A + (size_t)(bm + srow) * K + sj * 8;
    const float* Bg = B + (size_t)(bn + srow) * K + sj * 8;

    // Precomputed staging scatter bases (fragment layout).
    const int mt = srow >> 4, rr = srow & 15;
    const int abase = (mt * 32 + (rr & 7) * 4) * 4 + (rr >> 3) + 2 * sj;
    const int nt = srow >> 3, nn = srow & 7;
    const int bbase = (nt * 32 + nn * 4) * 2 + sj;

    float c[4][4][4];
#pragma unroll
    for (int i = 0; i < 4; i++)
#pragma unroll
        for (int j = 0; j < 4; j++)
#pragma unroll
            for (int r = 0; r < 4; r++) c[i][j][r] = 0.f;

    // Prefetch first slab
    float4 pa0 = *(const float4*)(Ag);
    float4 pa1 = *(const float4*)(Ag + 4);
    float4 pb0 = *(const float4*)(Bg);
    float4 pb1 = *(const float4*)(Bg + 4);

    for (int k0 = 0; k0 < K; k0 += 16) {
        // Split + scatter current slab into fragment-layout smem
        {
            float af[8] = {pa0.x, pa0.y, pa0.z, pa0.w, pa1.x, pa1.y, pa1.z, pa1.w};
            float bf[8] = {pb0.x, pb0.y, pb0.z, pb0.w, pb1.x, pb1.y, pb1.z, pb1.w};
#pragma unroll
            for (int t = 0; t < 4; t++) {
                unsigned hi, lo;
                split2_bf16(af[2 * t], af[2 * t + 1], hi, lo);
                Ah[abase + 4 * t] = hi;
                Al[abase + 4 * t] = lo;
                split2_bf16(bf[2 * t], bf[2 * t + 1], hi, lo);
                Bh[bbase + 2 * t] = hi;
                Bl[bbase + 2 * t] = lo;
            }
        }
        __syncthreads();

        // Prefetch next slab (overlaps with MMA compute)
        if (k0 + 16 < K) {
            pa0 = *(const float4*)(Ag + k0 + 16);
            pa1 = *(const float4*)(Ag + k0 + 20);
            pb0 = *(const float4*)(Bg + k0 + 16);
            pb1 = *(const float4*)(Bg + k0 + 20);
        }

        // Load fragments
        uint4 fah[4], fal[4];
        uint2 fbh[4], fbl[4];
#pragma unroll
        for (int i = 0; i < 4; i++) {
            fah[i] = *(const uint4*)&Ah[((warp_m * 4 + i) * 32 + lane) * 4];
            fal[i] = *(const uint4*)&Al[((warp_m * 4 + i) * 32 + lane) * 4];
        }
#pragma unroll
        for (int j = 0; j < 4; j++) {
            fbh[j] = *(const uint2*)&Bh[((warp_n * 4 + j) * 32 + lane) * 2];
            fbl[j] = *(const uint2*)&Bl[((warp_n * 4 + j) * 32 + lane) * 2];
        }

        // 16 accumulator tiles x 3 split terms
#pragma unroll
        for (int i = 0; i < 4; i++)
#pragma unroll
            for (int j = 0; j < 4; j++) {
                mma16816(c[i][j], &fah[i].x, &fbh[j].x);
                mma16816(c[i][j], &fal[i].x, &fbh[j].x);
                mma16816(c[i][j], &fah[i].x, &fbl[j].x);
            }
        __syncthreads();
    }

    // Epilogue
#pragma unroll
    for (int i = 0; i < 4; i++) {
        int row = bm + warp_m * 64 + i * 16 + (lane >> 2);
#pragma unroll
        for (int j = 0; j < 4; j++) {
            int col = bn + warp_n * 32 + j * 8 + (lane & 3) * 2;
            *(float2*)(C + (size_t)row * N + col) =
                make_float2(c[i][j][0], c[i][j][1]);
            *(float2*)(C + (size_t)(row + 8) * N + col) =
                make_float2(c[i][j][2], c[i][j][3]);
        }
    }
}

// ---------------------------------------------------------------------------
// SGEMM 64x64x16 with N bounds + column remap (for x_dbl layout). fp32.
// ---------------------------------------------------------------------------
__global__ __launch_bounds__(256) void sgemm64(
    const float* __restrict__ A, const float* __restrict__ B,
    float* __restrict__ C, int M, int N, int K, int ldc, int remap)
{
    __shared__ float As[16][68];
    __shared__ float Bs[16][68];

    const int tid = threadIdx.x;
    const int bm = blockIdx.y * 64;
    const int bn = blockIdx.x * 64;

    const int lr = tid >> 2;
    const int lk = (tid & 3) * 4;
    const int tx = tid & 15, ty = tid >> 4;

    float c[4][4];
#pragma unroll
    for (int i = 0; i < 4; i++)
#pragma unroll
        for (int j = 0; j < 4; j++) c[i][j] = 0.f;

    const float* Ag = A + (size_t)(bm + lr) * K + lk;
    const int brow = bn + lr;
    const float* Bg = B + (size_t)brow * K + lk;
    const bool bok = (brow < N);

    for (int k0 = 0; k0 < K; k0 += 16) {
        float4 av = *(const float4*)(Ag + k0);
        float4 bv = bok ? *(const float4*)(Bg + k0)
                        : make_float4(0.f, 0.f, 0.f, 0.f);
        As[lk + 0][lr] = av.x; As[lk + 1][lr] = av.y;
        As[lk + 2][lr] = av.z; As[lk + 3][lr] = av.w;
        Bs[lk + 0][lr] = bv.x; Bs[lk + 1][lr] = bv.y;
        Bs[lk + 2][lr] = bv.z; Bs[lk + 3][lr] = bv.w;
        __syncthreads();

#pragma unroll
        for (int k = 0; k < 16; k++) {
            float4 a = *(const float4*)&As[k][ty * 4];
            float4 b = *(const float4*)&Bs[k][tx * 4];
            float ar[4] = {a.x, a.y, a.z, a.w};
            float br[4] = {b.x, b.y, b.z, b.w};
#pragma unroll
            for (int i = 0; i < 4; i++)
#pragma unroll
                for (int j = 0; j < 4; j++)
                    c[i][j] = fmaf(ar[i], br[j], c[i][j]);
        }
        __syncthreads();
    }

#pragma unroll
    for (int i = 0; i < 4; i++) {
        int row = bm + ty * 4 + i;
#pragma unroll
        for (int j = 0; j < 4; j++) {
            int n = bn + tx * 4 + j;
            if (n < N) {
                int col = remap ? ((n == 0) ? 0 : n + 1) : n;
                C[(size_t)row * ldc + col] = c[i][j];
            }
        }
    }
}

// ---------------------------------------------------------------------------
// Causal conv (width 4) + SiLU
// ---------------------------------------------------------------------------
__global__ void conv_silu_kernel(const float* __restrict__ cw,
                                 const float* __restrict__ cb)
{
    int i = blockIdx.x * blockDim.x + threadIdx.x;
    const int ngrp = DINNER / 4;
    if (i >= MROWS * ngrp) return;
    int m  = i / ngrp;
    int dg = i % ngrp;
    int l  = m % SEQLEN;
    int d0 = dg * 4;

    float4 acc = make_float4(cb[d0], cb[d0 + 1], cb[d0 + 2], cb[d0 + 3]);
#pragma unroll
    for (int t = 0; t < 4; t++) {
        int li = l - 3 + t;
        if (li >= 0) {
            const float4 v = *(const float4*)&g_xz[(size_t)(m - l + li) * (2 * DINNER) + d0];
            acc.x = fmaf(v.x, __ldg(&cw[(d0 + 0) * 4 + t]), acc.x);
            acc.y = fmaf(v.y, __ldg(&cw[(d0 + 1) * 4 + t]), acc.y);
            acc.z = fmaf(v.z, __ldg(&cw[(d0 + 2) * 4 + t]), acc.z);
            acc.w = fmaf(v.w, __ldg(&cw[(d0 + 3) * 4 + t]), acc.w);
        }
    }
    float4 o;
    o.x = acc.x / (1.f + expf(-acc.x));
    o.y = acc.y / (1.f + expf(-acc.y));
    o.z = acc.z / (1.f + expf(-acc.z));
    o.w = acc.w / (1.f + expf(-acc.w));
    ((float4*)g_xconv)[i] = o;
}

// ---------------------------------------------------------------------------
// Precompute per-(m,d): {dt, dt*xc, D*xc*silu(z), silu(z)}
// ---------------------------------------------------------------------------
__global__ void pre_kernel(const float* __restrict__ dt_w,
                           const float* __restrict__ dt_b,
                           const float* __restrict__ Dp)
{
    int i = blockIdx.x * blockDim.x + threadIdx.x;
    if (i >= MROWS * DINNER) return;
    int m = i / DINNER, d = i % DINNER;

    float dtin = g_xdbl[(size_t)m * XDBL_LD];
    float xarg = fmaf(dtin, __ldg(&dt_w[d]), __ldg(&dt_b[d]));
    float dt = fmaxf(xarg, 0.f) + log1pf(expf(-fabsf(xarg)));

    float xc = g_xconv[i];
    float z  = g_xz[(size_t)m * (2 * DINNER) + DINNER + d];
    float sz = z / (1.f + expf(-z));

    float4 o = make_float4(dt, dt * xc, __ldg(&Dp[d]) * xc * sz, sz);
    ((float4*)g_pre)[i] = o;
}

// ---------------------------------------------------------------------------
// Selective scan: one warp per (b,d) channel, 2 states per lane.
// ---------------------------------------------------------------------------
__device__ __forceinline__ float fast_ex2(float x) {
    float r;
    asm("ex2.approx.ftz.f32 %0, %1;" : "=f"(r) : "f"(x));
    return r;
}

__global__ __launch_bounds__(256) void scan_kernel(const float* __restrict__ A_log)
{
    const int warp = threadIdx.x >> 5;
    const int lane = threadIdx.x & 31;
    const int ch = blockIdx.x * 8 + warp;
    const int b = ch / DINNER;
    const int d = ch % DINNER;
    const int n0 = 2 * lane;

    const float LOG2E = 1.4426950408889634f;
    const float An0 = -expf(A_log[n0])     * LOG2E;
    const float An1 = -expf(A_log[n0 + 1]) * LOG2E;

    const int mbase = b * SEQLEN;
    const float4* prp = (const float4*)g_pre + ((size_t)mbase * DINNER + d);
    const float*  xb  = g_xdbl + (size_t)mbase * XDBL_LD;
    float*        yo  = g_y + (size_t)mbase * DINNER + d;

    float h0 = 0.f, h1 = 0.f;
    float4 pr = __ldg(prp);
    float2 Bv = __ldg((const float2*)(xb + 2  + n0));
    float2 Cv = __ldg((const float2*)(xb + 66 + n0));

    for (int l = 0; l < SEQLEN; l++) {
        int ln = (l < SEQLEN - 1) ? (l + 1) : l;
        float4 prn = __ldg(prp + (size_t)ln * DINNER);
        float2 Bvn = __ldg((const float2*)(xb + (size_t)ln * XDBL_LD + 2  + n0));
        float2 Cvn = __ldg((const float2*)(xb + (size_t)ln * XDBL_LD + 66 + n0));

        float dA0 = fast_ex2(pr.x * An0);
        float dA1 = fast_ex2(pr.x * An1);
        h0 = fmaf(h0, dA0, Bv.x * pr.y);
        h1 = fmaf(h1, dA1, Bv.y * pr.y);
        float y = fmaf(h0, Cv.x, h1 * Cv.y);
#pragma unroll
        for (int o = 16; o > 0; o >>= 1)
            y += __shfl_xor_sync(0xffffffffu, y, o);
        if (lane == 0)
            yo[(size_t)l * DINNER] = fmaf(y, pr.w, pr.z);

        pr = prn; Bv = Bvn; Cv = Cvn;
    }
}

// ---------------------------------------------------------------------------
extern "C" void kernel_launch(void* const* d_in, const int* in_sizes, int n_in,
                              void* d_out, int out_size)
{
    const float* x      = (const float*)d_in[0];
    const float* W_in   = (const float*)d_in[1];
    const float* conv_w = (const float*)d_in[2];
    const float* conv_b = (const float*)d_in[3];
    const float* W_x    = (const float*)d_in[4];
    const float* dt_w   = (const float*)d_in[5];
    const float* dt_b   = (const float*)d_in[6];
    const float* A_log  = (const float*)d_in[7];
    const float* D_par  = (const float*)d_in[8];
    const float* W_out  = (const float*)d_in[9];
    float* out = (float*)d_out;

    float *p_xz, *p_xconv, *p_xdbl, *p_y;
    cudaGetSymbolAddress((void**)&p_xz,    g_xz);
    cudaGetSymbolAddress((void**)&p_xconv, g_xconv);
    cudaGetSymbolAddress((void**)&p_xdbl,  g_xdbl);
    cudaGetSymbolAddress((void**)&p_y,     g_y);

    // 1) xz = x @ W_in^T : [2048,3072]  (tensor cores, bf16x3)
    gemm_bf16x3<<<dim3(2 * DINNER / 128, MROWS / 128), 256>>>(
        x, W_in, p_xz, MROWS, 2 * DINNER, DMODEL);

    // 2) causal conv + silu
    {
        int total = MROWS * (DINNER / 4);
        conv_silu_kernel<<<(total + 255) / 256, 256>>>(conv_w, conv_b);
    }

    // 3) x_dbl = x_conv @ W_x^T : [2048,129] -> g_xdbl (remapped cols)
    sgemm64<<<dim3((129 + 63) / 64, MROWS / 64), 256>>>(
        p_xconv, W_x, p_xdbl, MROWS, 129, DINNER, XDBL_LD, 1);

    // 4) precompute dt / dt*xc / D*xc*silu(z) / silu(z)
    {
        int total = MROWS * DINNER;
        pre_kernel<<<(total + 255) / 256, 256>>>(dt_w, dt_b, D_par);
    }

    // 5) selective scan -> g_y (gated by silu(z), D term folded in)
    scan_kernel<<<(BATCH * DINNER) / 8, 256>>>(A_log);

    // 6) out = y @ W_out^T : [2048,768]  (tensor cores, bf16x3)
    gemm_bf16x3<<<dim3(DMODEL / 128, MROWS / 128), 256>>>(
        p_y, W_out, out, MROWS, DMODEL, DINNER);
}